// round 10
// baseline (speedup 1.0000x reference)
#include <cuda_runtime.h>

#define ELN 512
#define NIMG 128
#define BIMG 64
#define IMG_PIX (ELN*ELN)
#define KXP 264              // padded half-spectrum width (257 used, 8-col blocks)
#define AROWS 258            // stored rows of rolled-AC spectrum (u = 0..257)
#define BAND_LO 136          // mask band: |u-256| <= 120
#define BAND_HI 376
#define BAND_N  (BAND_HI - BAND_LO + 1)
#define TWO_PI 6.28318530717958647692f

// Scratch (device globals; zero-initialized at load, padding never written)
__device__ float2 g_bufB[(size_t)NIMG * KXP * ELN];    // [img][kx 0..263][y]
__device__ float2 g_bufA[(size_t)NIMG * AROWS * KXP];  // [img][u 0..257][kx]
__device__ float  g_ac[(size_t)NIMG * IMG_PIX];
__device__ unsigned int g_mm[2 * NIMG];
__device__ double g_diff;

// XOR swizzle: conflict-free for (t+64p) reads and (8t+q)/(k+64j+8q) writes
#define SW(i) ((i) ^ ((i) >> 3))

// ---- monotone float <-> uint encoding for atomic min/max ----
__device__ __forceinline__ unsigned fenc(float f) {
    unsigned u = __float_as_uint(f);
    return (u & 0x80000000u) ? ~u : (u | 0x80000000u);
}
__device__ __forceinline__ float fdec(unsigned e) {
    return __uint_as_float((e & 0x80000000u) ? (e ^ 0x80000000u) : ~e);
}

__device__ __forceinline__ float2 cadd(float2 a, float2 b){ return make_float2(a.x+b.x, a.y+b.y); }
__device__ __forceinline__ float2 csub(float2 a, float2 b){ return make_float2(a.x-b.x, a.y-b.y); }
__device__ __forceinline__ float2 cmul(float2 a, float2 b){
    return make_float2(fmaf(a.x, b.x, -a.y*b.y), fmaf(a.x, b.y, a.y*b.x));
}
template<int SGN>
__device__ __forceinline__ float2 mul_si(float2 a){
    return (SGN > 0) ? make_float2(-a.y, a.x) : make_float2(a.y, -a.x);
}

// 8-point DFT in registers
template<int SGN>
__device__ __forceinline__ void dft8(float2* x){
    const float C = 0.70710678118654752440f;
    const float sg = (float)SGN;
    float2 F0 = cadd(x[0], x[4]), F1 = csub(x[0], x[4]);
    float2 G0 = cadd(x[2], x[6]), G1r = mul_si<SGN>(csub(x[2], x[6]));
    float2 H0 = cadd(x[1], x[5]), H1 = csub(x[1], x[5]);
    float2 I0 = cadd(x[3], x[7]), I1r = mul_si<SGN>(csub(x[3], x[7]));
    float2 E0 = cadd(F0, G0), E2 = csub(F0, G0);
    float2 E1 = cadd(F1, G1r), E3 = csub(F1, G1r);
    float2 O0 = cadd(H0, I0), O2 = csub(H0, I0);
    float2 O1 = cadd(H1, I1r), O3 = csub(H1, I1r);
    float2 W1O = make_float2(C*(O1.x - sg*O1.y), C*(O1.y + sg*O1.x));
    float2 W2O = make_float2(-sg*O2.y, sg*O2.x);
    float2 W3O = make_float2(C*(-O3.x - sg*O3.y), C*(sg*O3.x - O3.y));
    x[0] = cadd(E0, O0);  x[4] = csub(E0, O0);
    x[1] = cadd(E1, W1O); x[5] = csub(E1, W1O);
    x[2] = cadd(E2, W2O); x[6] = csub(E2, W2O);
    x[3] = cadd(E3, W3O); x[7] = csub(E3, W3O);
}

template<int SGN>
__device__ __forceinline__ void twiddle(float2* x, int j, float invL8){
    float ang = (float)SGN * TWO_PI * invL8 * (float)j;
    float s, c; __sincosf(ang, &s, &c);
    float2 w = make_float2(c, s), wq = w;
    x[1] = cmul(x[1], wq);
#pragma unroll
    for (int q = 2; q < 8; q++) { wq = cmul(wq, w); x[q] = cmul(x[q], wq); }
}

// Stage 1 (L=64,M=1): x in regs -> dft8 -> twiddle(j=t) -> smem dst[8t+q]
template<int SGN>
__device__ __forceinline__ void stage1(float2* x, float2* dst, int t){
    dft8<SGN>(x);
    twiddle<SGN>(x, t, 1.0f / 512.0f);
#pragma unroll
    for (int q = 0; q < 8; q++) dst[SW(8*t + q)] = x[q];
}
// Stage 2 (L=8,M=8): read src[t+64p] -> dft8 -> twiddle(j=t>>3) -> dst[k+64j+8q]
template<int SGN>
__device__ __forceinline__ void stage2(const float2* src, float2* dst, int t){
    float2 x[8];
#pragma unroll
    for (int p = 0; p < 8; p++) x[p] = src[SW(t + 64*p)];
    dft8<SGN>(x);
    twiddle<SGN>(x, t >> 3, 1.0f / 64.0f);
    int base = (t & 7) + 64 * (t >> 3);
#pragma unroll
    for (int q = 0; q < 8; q++) dst[SW(base + 8*q)] = x[q];
}
// Stage 3 (L=1,M=64): read src[t+64p] -> dft8. Result x[q] = element (t+64q).
template<int SGN>
__device__ __forceinline__ void stage3(const float2* src, float2* x, int t){
#pragma unroll
    for (int p = 0; p < 8; p++) x[p] = src[SW(t + 64*p)];
    dft8<SGN>(x);
}

// ---- init accumulators (graph-replay safe) ----
__global__ void k_init() {
    int i = threadIdx.x;
    if (i < NIMG) { g_mm[2*i] = 0xFFFFFFFFu; g_mm[2*i + 1] = 0u; }
    if (i == 0) g_diff = 0.0;
}

// ---- K1: raw-copy rows to output (L1-resident), zero out-of-band AC slots,
//      mf0 + forward x-FFT of 2 packed real rows per FFT.
//      Writes half-spectrum kx=0..256 transposed -> g_bufB [img][kx][y]. ----
__global__ __launch_bounds__(256) void k_fwd_x(const float* __restrict__ in0,
                                               const float* __restrict__ in1,
                                               float* __restrict__ out) {
    __shared__ float2 sA[4][ELN], sB[4][ELN];
    int tid = threadIdx.x, f = tid >> 6, t = tid & 63;
    int g = blockIdx.x, img = blockIdx.y;
    int y0 = g * 8;
    const float* src = (img < BIMG) ? in0 + (size_t)img * IMG_PIX
                                    : in1 + (size_t)(img - BIMG) * IMG_PIX;
    // raw-input copy into concat output (reads hit L1; rows loaded below too)
    float* obase = out + 1 + (size_t)img * (ELN * 1024);
    for (int i = tid; i < 8 * ELN; i += 256) {
        int row = y0 + (i >> 9), col = i & 511;
        obase[(size_t)row * 1024 + col] = src[(size_t)row * ELN + col];
    }
    // zero AC slots for out-of-band rows
#pragma unroll
    for (int row = 0; row < 8; row++) {
        int r = y0 + row;
        if (r < BAND_LO || r > BAND_HI) {
            for (int c = tid; c < ELN; c += 256)
                obase[(size_t)r * 1024 + 512 + c] = 0.0f;
        }
    }

    const float* ra = src + (size_t)(y0 + 2*f) * ELN;
    const float* rb = ra + ELN;
    float2 x[8];
#pragma unroll
    for (int p = 0; p < 8; p++) {
        float va = ra[t + 64*p], vb = rb[t + 64*p];
        x[p] = make_float2(__expf(-8.0f * va * va), __expf(-8.0f * vb * vb));
    }
    stage1<-1>(x, sA[f], t);
    __syncthreads();
    stage2<-1>(sA[f], sB[f], t);
    __syncthreads();
    stage3<-1>(sB[f], x, t);
#pragma unroll
    for (int q = 0; q < 8; q++) sA[f][SW(t + 64*q)] = x[q];
    __syncthreads();

    float2* ob = g_bufB + (size_t)img * KXP * ELN;
    for (int kx = tid; kx <= 256; kx += 256) {
        int m = (ELN - kx) & (ELN - 1);
        float4* o = (float4*)(ob + (size_t)kx * ELN + y0);
#pragma unroll
        for (int f2 = 0; f2 < 4; f2++) {
            float2 z  = sA[f2][SW(kx)];
            float2 zm = sA[f2][SW(m)];
            // F_A = (Z + conj(Zm))/2 ; F_B = (Z - conj(Zm))/(2i)
            o[f2] = make_float4(0.5f*(z.x + zm.x), 0.5f*(z.y - zm.y),
                                0.5f*(z.y + zm.y), 0.5f*(zm.x - z.x));
        }
    }
}

// ---- K2: per 64-thread unit: 2 sequential fwd y-FFTs (cols 2f, 2f+1),
//      power (real) packed into ONE inverse y-FFT (z = P0 + i*P1).
//      Unpack via Z(u)/conj(Z(-u)), transposed write with y-roll,
//      rows u <= 257 kept -> g_bufA [img][u][kx]. 8 columns per block. ----
__global__ __launch_bounds__(256) void k_mid() {
    __shared__ float2 sA[4][ELN], sB[4][ELN];
    __shared__ float  sP[4][ELN];
    int tid = threadIdx.x, f = tid >> 6, t = tid & 63;
    int g = blockIdx.x, img = blockIdx.y;
    int kx0 = g * 8;
    const float2* ib0 = g_bufB + (size_t)img * KXP * ELN + (size_t)(kx0 + 2*f) * ELN;
    const float2* ib1 = ib0 + ELN;
    float2 x[8];
    // forward FFT of column c0 -> power0 to sP
#pragma unroll
    for (int p = 0; p < 8; p++) x[p] = ib0[t + 64*p];
    stage1<-1>(x, sA[f], t);
    __syncthreads();
    stage2<-1>(sA[f], sB[f], t);
    __syncthreads();
    stage3<-1>(sB[f], x, t);
#pragma unroll
    for (int q = 0; q < 8; q++)
        sP[f][t + 64*q] = fmaf(x[q].x, x[q].x, x[q].y * x[q].y);
    // forward FFT of column c1
#pragma unroll
    for (int p = 0; p < 8; p++) x[p] = ib1[t + 64*p];
    stage1<-1>(x, sA[f], t);
    __syncthreads();
    stage2<-1>(sA[f], sB[f], t);
    __syncthreads();
    stage3<-1>(sB[f], x, t);
    // z = P0 + i*P1 (same-thread sP readback), single packed inverse FFT
#pragma unroll
    for (int q = 0; q < 8; q++)
        x[q] = make_float2(sP[f][t + 64*q], fmaf(x[q].x, x[q].x, x[q].y * x[q].y));
    stage1<1>(x, sA[f], t);
    __syncthreads();
    stage2<1>(sA[f], sB[f], t);
    __syncthreads();
    stage3<1>(sB[f], x, t);
#pragma unroll
    for (int q = 0; q < 8; q++) sA[f][SW(t + 64*q)] = x[q];
    __syncthreads();

    float2* ob = g_bufA + (size_t)img * AROWS * KXP;
#pragma unroll
    for (int it = 0; it < 2; it++) {
        int y = tid + it * 256;
        int u = y ^ 256;                 // rolled row index
        if (u <= 257) {
            int ym = (ELN - y) & (ELN - 1);
            float2* o = ob + (size_t)u * KXP + kx0;
#pragma unroll
            for (int f2 = 0; f2 < 4; f2++) {
                float2 Zy = sA[f2][SW(y)], Zm = sA[f2][SW(ym)];
                // G0 = (Z + conj(Zm))/2 ; G1 = (Z - conj(Zm))/(2i)
                o[2*f2]     = make_float2(0.5f*(Zy.x + Zm.x), 0.5f*(Zy.y - Zm.y));
                o[2*f2 + 1] = make_float2(0.5f*(Zy.y + Zm.y), 0.5f*(Zm.x - Zy.x));
            }
        }
    }
}

// ---- K3: inverse x-FFT of rows u=0..257 only (2 rows per FFT, Hermitian
//      packing). Full min/max from these rows (others are mirror duplicates).
//      Band rows [136,376] written to g_ac directly + via inversion mirror. ----
__global__ __launch_bounds__(256) void k_inv_x() {
    __shared__ float2 sA[4][ELN], sB[4][ELN];
    __shared__ float smn[8], smx[8];
    int tid = threadIdx.x, f = tid >> 6, t = tid & 63;
    int g = blockIdx.x, img = blockIdx.y;
    int p0 = min(g * 4, 125);            // pair index base (pairs 0..128)
    int u0 = p0 * 2;
    const float2* Ga = g_bufA + (size_t)img * AROWS * KXP + (size_t)(u0 + 2*f) * KXP;
    const float2* Gb = Ga + KXP;
    float2 x[8];
#pragma unroll
    for (int p = 0; p < 8; p++) {
        int kx = t + 64*p;
        if (kx <= 256) {
            float2 a = Ga[kx], b = Gb[kx];
            x[p] = make_float2(a.x - b.y, a.y + b.x);     // Ga + i*Gb
        } else {
            int m = ELN - kx;
            float2 a = Ga[m], b = Gb[m];
            x[p] = make_float2(a.x + b.y, b.x - a.y);     // conj(Ga) + i*conj(Gb)
        }
    }
    stage1<1>(x, sA[f], t);
    __syncthreads();
    stage2<1>(sA[f], sB[f], t);
    __syncthreads();
    stage3<1>(sB[f], x, t);
#pragma unroll
    for (int q = 0; q < 8; q++) sA[f][SW(t + 64*q)] = x[q];
    __syncthreads();

    float* ob = g_ac + (size_t)img * IMG_PIX;
    float lmin = 3.4e38f, lmax = -3.4e38f;
#pragma unroll
    for (int it = 0; it < 16; it++) {
        int idx = tid + it * 256;        // 0..4095 = 8 rows x 512
        int r8 = idx >> 9, xx = idx & 511;
        float2 v2 = sA[r8 >> 1][SW(xx)];
        float v = (r8 & 1) ? v2.y : v2.x;
        int u = u0 + r8;                 // 0..257
        int vcol = xx ^ 256;
        if (u >= BAND_LO) ob[(size_t)u * ELN + vcol] = v;       // u <= 257 < BAND_HI
        int um = (ELN - u) & (ELN - 1);  // mirror row
        if (um != u && um >= BAND_LO && um <= BAND_HI)
            ob[(size_t)um * ELN + ((ELN - vcol) & (ELN - 1))] = v;
        lmin = fminf(lmin, v);
        lmax = fmaxf(lmax, v);
    }
#pragma unroll
    for (int off = 16; off; off >>= 1) {
        lmin = fminf(lmin, __shfl_down_sync(0xFFFFFFFFu, lmin, off));
        lmax = fmaxf(lmax, __shfl_down_sync(0xFFFFFFFFu, lmax, off));
    }
    int wid = tid >> 5, lane = tid & 31;
    if (lane == 0) { smn[wid] = lmin; smx[wid] = lmax; }
    __syncthreads();
    if (tid == 0) {
        float mn = smn[0], mx = smx[0];
#pragma unroll
        for (int w = 1; w < 8; w++) { mn = fminf(mn, smn[w]); mx = fmaxf(mx, smx[w]); }
        atomicMin(&g_mm[2 * img],     fenc(mn));
        atomicMax(&g_mm[2 * img + 1], fenc(mx));
    }
}

// ---- K4: band rows only: normalize + mask + MSE partial + AC writes ----
__global__ __launch_bounds__(256) void k_out(float* __restrict__ out) {
    __shared__ float red[8];
    int r = BAND_LO + blockIdx.x, b = blockIdx.y, tid = threadIdx.x;
    float mnI = fdec(g_mm[2 * b]),          mxI = fdec(g_mm[2 * b + 1]);
    float mnT = fdec(g_mm[2 * (b + BIMG)]), mxT = fdec(g_mm[2 * (b + BIMG) + 1]);
    float sI = 1.0f / (mxI - mnI + 1e-12f);
    float sT = 1.0f / (mxT - mnT + 1e-12f);
    const float* ain = g_ac + (size_t)b * IMG_PIX + (size_t)r * ELN;
    const float* atg = g_ac + (size_t)(b + BIMG) * IMG_PIX + (size_t)r * ELN;
    float* o1 = out + 1 + (size_t)b * (ELN * 1024) + (size_t)r * 1024 + ELN;
    float* o2 = o1 + (size_t)BIMG * (ELN * 1024);
    float dy = (float)(r - 256);
    float acc = 0.0f;
#pragma unroll
    for (int c = tid; c < ELN; c += 256) {
        float dx = (float)(c - 256);
        float mask = __expf(-(dx * dx + dy * dy) * (1.0f / 800.0f));
        float ia = (ain[c] - mnI) * sI * mask;
        float ta = (atg[c] - mnT) * sT * mask;
        float d = ia - ta;
        acc += d * d;
        o1[c] = ia;
        o2[c] = ta;
    }
#pragma unroll
    for (int off = 16; off; off >>= 1)
        acc += __shfl_down_sync(0xFFFFFFFFu, acc, off);
    int wid = tid >> 5, lane = tid & 31;
    if (lane == 0) red[wid] = acc;
    __syncthreads();
    if (tid == 0) {
        float s = 0.0f;
#pragma unroll
        for (int w = 0; w < 8; w++) s += red[w];
        atomicAdd(&g_diff, (double)s);
    }
}

__global__ void k_fin(float* __restrict__ out) {
    out[0] = (float)(g_diff / (double)((size_t)BIMG * IMG_PIX));
}

extern "C" void kernel_launch(void* const* d_in, const int* in_sizes, int n_in,
                              void* d_out, int out_size) {
    const float* in0 = (const float*)d_in[0];   // input  (64,1,512,512)
    const float* in1 = (const float*)d_in[1];   // target (64,1,512,512)
    float* out = (float*)d_out;                 // [diff | input_and_ac | target_and_ac]

    k_init<<<1, 128>>>();
    k_fwd_x<<<dim3(64, NIMG), 256>>>(in0, in1, out);
    k_mid<<<dim3(33, NIMG), 256>>>();
    k_inv_x<<<dim3(33, NIMG), 256>>>();
    k_out<<<dim3(BAND_N, BIMG), 256>>>(out);
    k_fin<<<1, 1>>>(out);
}

// round 14
// speedup vs baseline: 1.1853x; 1.1853x over previous
#include <cuda_runtime.h>

#define ELN 512
#define NIMG 128
#define BIMG 64
#define IMG_PIX (ELN*ELN)
#define KXP 264              // padded half-spectrum width (257 used, 8-col blocks)
#define AROWS 258            // stored rows of rolled-AC spectrum (u = 0..257)
#define BAND_LO 136          // mask band: |u-256| <= 120
#define BAND_HI 376
#define TWO_PI 6.28318530717958647692f

// Scratch (device globals; zero-initialized at load, padding never written)
__device__ float2 g_bufB[(size_t)NIMG * KXP * ELN];    // [img][kx 0..263][y]
__device__ float2 g_bufA[(size_t)NIMG * AROWS * KXP];  // [img][u 0..257][kx]
__device__ float  g_ac[(size_t)NIMG * IMG_PIX];
__device__ unsigned int g_mm[2 * NIMG];
__device__ double g_diff;

// XOR swizzle: conflict-free for (t+64p) reads and (8t+q)/(k+64j+8q) writes
#define SW(i) ((i) ^ ((i) >> 3))

// ---- monotone float <-> uint encoding for atomic min/max ----
__device__ __forceinline__ unsigned fenc(float f) {
    unsigned u = __float_as_uint(f);
    return (u & 0x80000000u) ? ~u : (u | 0x80000000u);
}
__device__ __forceinline__ float fdec(unsigned e) {
    return __uint_as_float((e & 0x80000000u) ? (e ^ 0x80000000u) : ~e);
}

__device__ __forceinline__ float2 cadd(float2 a, float2 b){ return make_float2(a.x+b.x, a.y+b.y); }
__device__ __forceinline__ float2 csub(float2 a, float2 b){ return make_float2(a.x-b.x, a.y-b.y); }
__device__ __forceinline__ float2 cmul(float2 a, float2 b){
    return make_float2(fmaf(a.x, b.x, -a.y*b.y), fmaf(a.x, b.y, a.y*b.x));
}
template<int SGN>
__device__ __forceinline__ float2 mul_si(float2 a){
    return (SGN > 0) ? make_float2(-a.y, a.x) : make_float2(a.y, -a.x);
}

// 8-point DFT in registers
template<int SGN>
__device__ __forceinline__ void dft8(float2* x){
    const float C = 0.70710678118654752440f;
    const float sg = (float)SGN;
    float2 F0 = cadd(x[0], x[4]), F1 = csub(x[0], x[4]);
    float2 G0 = cadd(x[2], x[6]), G1r = mul_si<SGN>(csub(x[2], x[6]));
    float2 H0 = cadd(x[1], x[5]), H1 = csub(x[1], x[5]);
    float2 I0 = cadd(x[3], x[7]), I1r = mul_si<SGN>(csub(x[3], x[7]));
    float2 E0 = cadd(F0, G0), E2 = csub(F0, G0);
    float2 E1 = cadd(F1, G1r), E3 = csub(F1, G1r);
    float2 O0 = cadd(H0, I0), O2 = csub(H0, I0);
    float2 O1 = cadd(H1, I1r), O3 = csub(H1, I1r);
    float2 W1O = make_float2(C*(O1.x - sg*O1.y), C*(O1.y + sg*O1.x));
    float2 W2O = make_float2(-sg*O2.y, sg*O2.x);
    float2 W3O = make_float2(C*(-O3.x - sg*O3.y), C*(sg*O3.x - O3.y));
    x[0] = cadd(E0, O0);  x[4] = csub(E0, O0);
    x[1] = cadd(E1, W1O); x[5] = csub(E1, W1O);
    x[2] = cadd(E2, W2O); x[6] = csub(E2, W2O);
    x[3] = cadd(E3, W3O); x[7] = csub(E3, W3O);
}

template<int SGN>
__device__ __forceinline__ void twiddle(float2* x, int j, float invL8){
    float ang = (float)SGN * TWO_PI * invL8 * (float)j;
    float s, c; __sincosf(ang, &s, &c);
    float2 w = make_float2(c, s), wq = w;
    x[1] = cmul(x[1], wq);
#pragma unroll
    for (int q = 2; q < 8; q++) { wq = cmul(wq, w); x[q] = cmul(x[q], wq); }
}

// Stage 1 (L=64,M=1): x in regs -> dft8 -> twiddle(j=t) -> smem dst[8t+q]
template<int SGN>
__device__ __forceinline__ void stage1(float2* x, float2* dst, int t){
    dft8<SGN>(x);
    twiddle<SGN>(x, t, 1.0f / 512.0f);
#pragma unroll
    for (int q = 0; q < 8; q++) dst[SW(8*t + q)] = x[q];
}
// Stage 2 (L=8,M=8): read src[t+64p] -> dft8 -> twiddle(j=t>>3) -> dst[k+64j+8q]
template<int SGN>
__device__ __forceinline__ void stage2(const float2* src, float2* dst, int t){
    float2 x[8];
#pragma unroll
    for (int p = 0; p < 8; p++) x[p] = src[SW(t + 64*p)];
    dft8<SGN>(x);
    twiddle<SGN>(x, t >> 3, 1.0f / 64.0f);
    int base = (t & 7) + 64 * (t >> 3);
#pragma unroll
    for (int q = 0; q < 8; q++) dst[SW(base + 8*q)] = x[q];
}
// Stage 3 (L=1,M=64): read src[t+64p] -> dft8. Result x[q] = element (t+64q).
template<int SGN>
__device__ __forceinline__ void stage3(const float2* src, float2* x, int t){
#pragma unroll
    for (int p = 0; p < 8; p++) x[p] = src[SW(t + 64*p)];
    dft8<SGN>(x);
}

// ---- init accumulators (graph-replay safe) ----
__global__ void k_init() {
    int i = threadIdx.x;
    if (i < NIMG) { g_mm[2*i] = 0xFFFFFFFFu; g_mm[2*i + 1] = 0u; }
    if (i == 0) g_diff = 0.0;
}

// ---- K1: mf0 + forward x-FFT of 2 packed real rows per FFT.
//      Writes half-spectrum kx=0..256 transposed -> g_bufB [img][kx][y]. ----
__global__ __launch_bounds__(256) void k_fwd_x(const float* __restrict__ in0,
                                               const float* __restrict__ in1) {
    __shared__ float2 sA[4][ELN], sB[4][ELN];
    int tid = threadIdx.x, f = tid >> 6, t = tid & 63;
    int g = blockIdx.x, img = blockIdx.y;
    int y0 = g * 8;
    const float* src = (img < BIMG) ? in0 + (size_t)img * IMG_PIX
                                    : in1 + (size_t)(img - BIMG) * IMG_PIX;
    const float* ra = src + (size_t)(y0 + 2*f) * ELN;
    const float* rb = ra + ELN;
    float2 x[8];
#pragma unroll
    for (int p = 0; p < 8; p++) {
        float va = ra[t + 64*p], vb = rb[t + 64*p];
        x[p] = make_float2(__expf(-8.0f * va * va), __expf(-8.0f * vb * vb));
    }
    stage1<-1>(x, sA[f], t);
    __syncthreads();
    stage2<-1>(sA[f], sB[f], t);
    __syncthreads();
    stage3<-1>(sB[f], x, t);
#pragma unroll
    for (int q = 0; q < 8; q++) sA[f][SW(t + 64*q)] = x[q];
    __syncthreads();

    float2* ob = g_bufB + (size_t)img * KXP * ELN;
    for (int kx = tid; kx <= 256; kx += 256) {
        int m = (ELN - kx) & (ELN - 1);
        float4* o = (float4*)(ob + (size_t)kx * ELN + y0);
#pragma unroll
        for (int f2 = 0; f2 < 4; f2++) {
            float2 z  = sA[f2][SW(kx)];
            float2 zm = sA[f2][SW(m)];
            // F_A = (Z + conj(Zm))/2 ; F_B = (Z - conj(Zm))/(2i)
            o[f2] = make_float4(0.5f*(z.x + zm.x), 0.5f*(z.y - zm.y),
                                0.5f*(z.y + zm.y), 0.5f*(zm.x - z.x));
        }
    }
}

// ---- K2: per 64-thread unit: 2 sequential fwd y-FFTs (cols 2f, 2f+1),
//      powers (real) packed into ONE inverse y-FFT (z = P0 + i*P1).
//      Unpack via Z(u)/conj(Z(-u)) into a float4 store, transposed with
//      y-roll, rows u <= 257 kept -> g_bufA [img][u][kx]. 8 cols/block. ----
__global__ __launch_bounds__(256) void k_mid() {
    __shared__ float2 sA[4][ELN], sB[4][ELN];
    __shared__ float  sP[4][ELN];
    int tid = threadIdx.x, f = tid >> 6, t = tid & 63;
    int g = blockIdx.x, img = blockIdx.y;
    int kx0 = g * 8;
    const float2* ib0 = g_bufB + (size_t)img * KXP * ELN + (size_t)(kx0 + 2*f) * ELN;
    const float2* ib1 = ib0 + ELN;
    float2 x[8];
    // forward FFT of column 2f -> power to sP
#pragma unroll
    for (int p = 0; p < 8; p++) x[p] = ib0[t + 64*p];
    stage1<-1>(x, sA[f], t);
    __syncthreads();
    stage2<-1>(sA[f], sB[f], t);
    __syncthreads();
    stage3<-1>(sB[f], x, t);
#pragma unroll
    for (int q = 0; q < 8; q++)
        sP[f][t + 64*q] = fmaf(x[q].x, x[q].x, x[q].y * x[q].y);
    // forward FFT of column 2f+1
#pragma unroll
    for (int p = 0; p < 8; p++) x[p] = ib1[t + 64*p];
    stage1<-1>(x, sA[f], t);
    __syncthreads();
    stage2<-1>(sA[f], sB[f], t);
    __syncthreads();
    stage3<-1>(sB[f], x, t);
    // z = P0 + i*P1 (same-thread sP readback), single packed inverse FFT
#pragma unroll
    for (int q = 0; q < 8; q++)
        x[q] = make_float2(sP[f][t + 64*q], fmaf(x[q].x, x[q].x, x[q].y * x[q].y));
    stage1<1>(x, sA[f], t);
    __syncthreads();
    stage2<1>(sA[f], sB[f], t);
    __syncthreads();
    stage3<1>(sB[f], x, t);
#pragma unroll
    for (int q = 0; q < 8; q++) sA[f][SW(t + 64*q)] = x[q];
    __syncthreads();

    float2* ob = g_bufA + (size_t)img * AROWS * KXP;
#pragma unroll
    for (int it = 0; it < 2; it++) {
        int y = tid + it * 256;
        int u = y ^ 256;                 // rolled row index
        if (u <= 257) {
            int ym = (ELN - y) & (ELN - 1);
            float4* o = (float4*)(ob + (size_t)u * KXP + kx0);
#pragma unroll
            for (int f2 = 0; f2 < 4; f2++) {
                float2 Zy = sA[f2][SW(y)], Zm = sA[f2][SW(ym)];
                // G0 = (Z + conj(Zm))/2 ; G1 = (Z - conj(Zm))/(2i)
                o[f2] = make_float4(0.5f*(Zy.x + Zm.x), 0.5f*(Zy.y - Zm.y),
                                    0.5f*(Zy.y + Zm.y), 0.5f*(Zm.x - Zy.x));
            }
        }
    }
}

// ---- K3: inverse x-FFT of rows u=0..257 only (2 rows per FFT, Hermitian
//      packing). Full min/max from these rows (others are mirror duplicates).
//      Band rows [136,376] written to g_ac directly + via inversion mirror. ----
__global__ __launch_bounds__(256) void k_inv_x() {
    __shared__ float2 sA[4][ELN], sB[4][ELN];
    __shared__ float smn[8], smx[8];
    int tid = threadIdx.x, f = tid >> 6, t = tid & 63;
    int g = blockIdx.x, img = blockIdx.y;
    int p0 = min(g * 4, 125);            // pair index base (pairs 0..128)
    int u0 = p0 * 2;
    const float2* Ga = g_bufA + (size_t)img * AROWS * KXP + (size_t)(u0 + 2*f) * KXP;
    const float2* Gb = Ga + KXP;
    float2 x[8];
#pragma unroll
    for (int p = 0; p < 8; p++) {
        int kx = t + 64*p;
        if (kx <= 256) {
            float2 a = Ga[kx], b = Gb[kx];
            x[p] = make_float2(a.x - b.y, a.y + b.x);     // Ga + i*Gb
        } else {
            int m = ELN - kx;
            float2 a = Ga[m], b = Gb[m];
            x[p] = make_float2(a.x + b.y, b.x - a.y);     // conj(Ga) + i*conj(Gb)
        }
    }
    stage1<1>(x, sA[f], t);
    __syncthreads();
    stage2<1>(sA[f], sB[f], t);
    __syncthreads();
    stage3<1>(sB[f], x, t);
#pragma unroll
    for (int q = 0; q < 8; q++) sA[f][SW(t + 64*q)] = x[q];
    __syncthreads();

    float* ob = g_ac + (size_t)img * IMG_PIX;
    float lmin = 3.4e38f, lmax = -3.4e38f;
#pragma unroll
    for (int it = 0; it < 16; it++) {
        int idx = tid + it * 256;        // 0..4095 = 8 rows x 512
        int r8 = idx >> 9, xx = idx & 511;
        float2 v2 = sA[r8 >> 1][SW(xx)];
        float v = (r8 & 1) ? v2.y : v2.x;
        int u = u0 + r8;                 // 0..257
        int vcol = xx ^ 256;
        if (u >= BAND_LO) ob[(size_t)u * ELN + vcol] = v;       // u <= 257 < BAND_HI
        int um = (ELN - u) & (ELN - 1);  // mirror row
        if (um != u && um >= BAND_LO && um <= BAND_HI)
            ob[(size_t)um * ELN + ((ELN - vcol) & (ELN - 1))] = v;
        lmin = fminf(lmin, v);
        lmax = fmaxf(lmax, v);
    }
#pragma unroll
    for (int off = 16; off; off >>= 1) {
        lmin = fminf(lmin, __shfl_down_sync(0xFFFFFFFFu, lmin, off));
        lmax = fmaxf(lmax, __shfl_down_sync(0xFFFFFFFFu, lmax, off));
    }
    int wid = tid >> 5, lane = tid & 31;
    if (lane == 0) { smn[wid] = lmin; smx[wid] = lmax; }
    __syncthreads();
    if (tid == 0) {
        float mn = smn[0], mx = smx[0];
#pragma unroll
        for (int w = 1; w < 8; w++) { mn = fminf(mn, smn[w]); mx = fmaxf(mx, smx[w]); }
        atomicMin(&g_mm[2 * img],     fenc(mn));
        atomicMax(&g_mm[2 * img + 1], fenc(mx));
    }
}

// ---- K4: normalize + mask + MSE partial + concat outputs.
//      Outside the mask band the AC output is < 1.5e-8 -> write exact 0. ----
__global__ __launch_bounds__(256) void k_out(const float* __restrict__ in0,
                                             const float* __restrict__ in1,
                                             float* __restrict__ out) {
    __shared__ float red[8];
    int r = blockIdx.x, b = blockIdx.y, tid = threadIdx.x;
    const float* rin = in0 + (size_t)b * IMG_PIX + (size_t)r * ELN;
    const float* rtg = in1 + (size_t)b * IMG_PIX + (size_t)r * ELN;
    float* o1 = out + 1 + (size_t)b * (ELN * 1024) + (size_t)r * 1024;
    float* o2 = o1 + (size_t)BIMG * (ELN * 1024);

    if (r < BAND_LO || r > BAND_HI) {
#pragma unroll
        for (int c = tid; c < ELN; c += 256) {
            o1[c] = rin[c];  o1[ELN + c] = 0.0f;
            o2[c] = rtg[c];  o2[ELN + c] = 0.0f;
        }
        return;
    }

    float mnI = fdec(g_mm[2 * b]),          mxI = fdec(g_mm[2 * b + 1]);
    float mnT = fdec(g_mm[2 * (b + BIMG)]), mxT = fdec(g_mm[2 * (b + BIMG) + 1]);
    float sI = 1.0f / (mxI - mnI + 1e-12f);
    float sT = 1.0f / (mxT - mnT + 1e-12f);
    const float* ain = g_ac + (size_t)b * IMG_PIX + (size_t)r * ELN;
    const float* atg = g_ac + (size_t)(b + BIMG) * IMG_PIX + (size_t)r * ELN;
    float dy = (float)(r - 256);
    float acc = 0.0f;
#pragma unroll
    for (int c = tid; c < ELN; c += 256) {
        float dx = (float)(c - 256);
        float mask = __expf(-(dx * dx + dy * dy) * (1.0f / 800.0f));
        float ia = (ain[c] - mnI) * sI * mask;
        float ta = (atg[c] - mnT) * sT * mask;
        float d = ia - ta;
        acc += d * d;
        o1[c] = rin[c];  o1[ELN + c] = ia;
        o2[c] = rtg[c];  o2[ELN + c] = ta;
    }
#pragma unroll
    for (int off = 16; off; off >>= 1)
        acc += __shfl_down_sync(0xFFFFFFFFu, acc, off);
    int wid = tid >> 5, lane = tid & 31;
    if (lane == 0) red[wid] = acc;
    __syncthreads();
    if (tid == 0) {
        float s = 0.0f;
#pragma unroll
        for (int w = 0; w < 8; w++) s += red[w];
        atomicAdd(&g_diff, (double)s);
    }
}

__global__ void k_fin(float* __restrict__ out) {
    out[0] = (float)(g_diff / (double)((size_t)BIMG * IMG_PIX));
}

extern "C" void kernel_launch(void* const* d_in, const int* in_sizes, int n_in,
                              void* d_out, int out_size) {
    const float* in0 = (const float*)d_in[0];   // input  (64,1,512,512)
    const float* in1 = (const float*)d_in[1];   // target (64,1,512,512)
    float* out = (float*)d_out;                 // [diff | input_and_ac | target_and_ac]

    k_init<<<1, 128>>>();
    k_fwd_x<<<dim3(64, NIMG), 256>>>(in0, in1);
    k_mid<<<dim3(33, NIMG), 256>>>();
    k_inv_x<<<dim3(33, NIMG), 256>>>();
    k_out<<<dim3(ELN, BIMG), 256>>>(in0, in1, out);
    k_fin<<<1, 1>>>(out);
}

// round 16
// speedup vs baseline: 1.2007x; 1.0130x over previous
#include <cuda_runtime.h>

#define ELN 512
#define NIMG 128
#define BIMG 64
#define IMG_PIX (ELN*ELN)
#define KXP 264              // padded half-spectrum width (257 used, 8-col blocks)
#define AROWS 258            // stored rows of rolled-AC spectrum (u = 0..257)
#define BAND_LO 136          // mask band: |u-256| <= 120
#define BAND_HI 376
#define TWO_PI 6.28318530717958647692f

// Scratch (device globals; zero-initialized at load, padding never written)
__device__ float2 g_bufB[(size_t)NIMG * KXP * ELN];    // [img][kx 0..263][y]
__device__ float2 g_bufA[(size_t)NIMG * AROWS * KXP];  // [img][u 0..257][kx]
__device__ float  g_ac[(size_t)NIMG * IMG_PIX];
__device__ unsigned int g_mm[2 * NIMG];
__device__ double g_diff;

// XOR swizzle: conflict-free for (t+64p) reads and (8t+q)/(k+64j+8q) writes
#define SW(i) ((i) ^ ((i) >> 3))

// ---- monotone float <-> uint encoding for atomic min/max ----
__device__ __forceinline__ unsigned fenc(float f) {
    unsigned u = __float_as_uint(f);
    return (u & 0x80000000u) ? ~u : (u | 0x80000000u);
}
__device__ __forceinline__ float fdec(unsigned e) {
    return __uint_as_float((e & 0x80000000u) ? (e ^ 0x80000000u) : ~e);
}

__device__ __forceinline__ float2 cadd(float2 a, float2 b){ return make_float2(a.x+b.x, a.y+b.y); }
__device__ __forceinline__ float2 csub(float2 a, float2 b){ return make_float2(a.x-b.x, a.y-b.y); }
__device__ __forceinline__ float2 cmul(float2 a, float2 b){
    return make_float2(fmaf(a.x, b.x, -a.y*b.y), fmaf(a.x, b.y, a.y*b.x));
}
template<int SGN>
__device__ __forceinline__ float2 mul_si(float2 a){
    return (SGN > 0) ? make_float2(-a.y, a.x) : make_float2(a.y, -a.x);
}

// 8-point DFT in registers
template<int SGN>
__device__ __forceinline__ void dft8(float2* x){
    const float C = 0.70710678118654752440f;
    const float sg = (float)SGN;
    float2 F0 = cadd(x[0], x[4]), F1 = csub(x[0], x[4]);
    float2 G0 = cadd(x[2], x[6]), G1r = mul_si<SGN>(csub(x[2], x[6]));
    float2 H0 = cadd(x[1], x[5]), H1 = csub(x[1], x[5]);
    float2 I0 = cadd(x[3], x[7]), I1r = mul_si<SGN>(csub(x[3], x[7]));
    float2 E0 = cadd(F0, G0), E2 = csub(F0, G0);
    float2 E1 = cadd(F1, G1r), E3 = csub(F1, G1r);
    float2 O0 = cadd(H0, I0), O2 = csub(H0, I0);
    float2 O1 = cadd(H1, I1r), O3 = csub(H1, I1r);
    float2 W1O = make_float2(C*(O1.x - sg*O1.y), C*(O1.y + sg*O1.x));
    float2 W2O = make_float2(-sg*O2.y, sg*O2.x);
    float2 W3O = make_float2(C*(-O3.x - sg*O3.y), C*(sg*O3.x - O3.y));
    x[0] = cadd(E0, O0);  x[4] = csub(E0, O0);
    x[1] = cadd(E1, W1O); x[5] = csub(E1, W1O);
    x[2] = cadd(E2, W2O); x[6] = csub(E2, W2O);
    x[3] = cadd(E3, W3O); x[7] = csub(E3, W3O);
}

template<int SGN>
__device__ __forceinline__ void twiddle(float2* x, int j, float invL8){
    float ang = (float)SGN * TWO_PI * invL8 * (float)j;
    float s, c; __sincosf(ang, &s, &c);
    float2 w = make_float2(c, s), wq = w;
    x[1] = cmul(x[1], wq);
#pragma unroll
    for (int q = 2; q < 8; q++) { wq = cmul(wq, w); x[q] = cmul(x[q], wq); }
}

// Stage 1 (L=64,M=1): x in regs -> dft8 -> twiddle(j=t) -> smem dst[8t+q]
template<int SGN>
__device__ __forceinline__ void stage1(float2* x, float2* dst, int t){
    dft8<SGN>(x);
    twiddle<SGN>(x, t, 1.0f / 512.0f);
#pragma unroll
    for (int q = 0; q < 8; q++) dst[SW(8*t + q)] = x[q];
}
// Stage 2 (L=8,M=8): read src[t+64p] -> dft8 -> twiddle(j=t>>3) -> dst[k+64j+8q]
template<int SGN>
__device__ __forceinline__ void stage2(const float2* src, float2* dst, int t){
    float2 x[8];
#pragma unroll
    for (int p = 0; p < 8; p++) x[p] = src[SW(t + 64*p)];
    dft8<SGN>(x);
    twiddle<SGN>(x, t >> 3, 1.0f / 64.0f);
    int base = (t & 7) + 64 * (t >> 3);
#pragma unroll
    for (int q = 0; q < 8; q++) dst[SW(base + 8*q)] = x[q];
}
// Stage 3 (L=1,M=64): read src[t+64p] -> dft8. Result x[q] = element (t+64q).
template<int SGN>
__device__ __forceinline__ void stage3(const float2* src, float2* x, int t){
#pragma unroll
    for (int p = 0; p < 8; p++) x[p] = src[SW(t + 64*p)];
    dft8<SGN>(x);
}

// ---- init accumulators (graph-replay safe) ----
__global__ void k_init() {
    int i = threadIdx.x;
    if (i < NIMG) { g_mm[2*i] = 0xFFFFFFFFu; g_mm[2*i + 1] = 0u; }
    if (i == 0) g_diff = 0.0;
}

// ---- K1: mf0 + forward x-FFT of 2 packed real rows per FFT.
//      Writes half-spectrum kx=0..256 transposed -> g_bufB [img][kx][y]. ----
__global__ __launch_bounds__(256) void k_fwd_x(const float* __restrict__ in0,
                                               const float* __restrict__ in1) {
    __shared__ float2 sA[4][ELN], sB[4][ELN];
    int tid = threadIdx.x, f = tid >> 6, t = tid & 63;
    int g = blockIdx.x, img = blockIdx.y;
    int y0 = g * 8;
    const float* src = (img < BIMG) ? in0 + (size_t)img * IMG_PIX
                                    : in1 + (size_t)(img - BIMG) * IMG_PIX;
    const float* ra = src + (size_t)(y0 + 2*f) * ELN;
    const float* rb = ra + ELN;
    float2 x[8];
#pragma unroll
    for (int p = 0; p < 8; p++) {
        float va = ra[t + 64*p], vb = rb[t + 64*p];
        x[p] = make_float2(__expf(-8.0f * va * va), __expf(-8.0f * vb * vb));
    }
    stage1<-1>(x, sA[f], t);
    __syncthreads();
    stage2<-1>(sA[f], sB[f], t);
    __syncthreads();
    stage3<-1>(sB[f], x, t);
#pragma unroll
    for (int q = 0; q < 8; q++) sA[f][SW(t + 64*q)] = x[q];
    __syncthreads();

    float2* ob = g_bufB + (size_t)img * KXP * ELN;
    for (int kx = tid; kx <= 256; kx += 256) {
        int m = (ELN - kx) & (ELN - 1);
        float4* o = (float4*)(ob + (size_t)kx * ELN + y0);
#pragma unroll
        for (int f2 = 0; f2 < 4; f2++) {
            float2 z  = sA[f2][SW(kx)];
            float2 zm = sA[f2][SW(m)];
            // F_A = (Z + conj(Zm))/2 ; F_B = (Z - conj(Zm))/(2i)
            o[f2] = make_float4(0.5f*(z.x + zm.x), 0.5f*(z.y - zm.y),
                                0.5f*(z.y + zm.y), 0.5f*(zm.x - z.x));
        }
    }
}

// ---- K2: per 64-thread unit: fwd y-FFT of col 2f (power kept in REGISTERS),
//      fwd y-FFT of col 2f+1, then ONE packed inverse y-FFT (z = P0 + i*P1).
//      stage3 output indexing (t+64q) == stage1 input indexing, so the
//      register carry needs no shared staging (occupancy preserved vs sP).
//      Unpack via Z(u)/conj(Z(-u)) into float4, transposed with y-roll,
//      rows u <= 257 kept -> g_bufA [img][u][kx]. 8 cols/block. ----
__global__ __launch_bounds__(256) void k_mid() {
    __shared__ float2 sA[4][ELN], sB[4][ELN];
    int tid = threadIdx.x, f = tid >> 6, t = tid & 63;
    int g = blockIdx.x, img = blockIdx.y;
    int kx0 = g * 8;
    const float2* ib0 = g_bufB + (size_t)img * KXP * ELN + (size_t)(kx0 + 2*f) * ELN;
    const float2* ib1 = ib0 + ELN;
    float2 x[8];
    float p0[8];
    // forward FFT of column 2f -> power to registers
#pragma unroll
    for (int p = 0; p < 8; p++) x[p] = ib0[t + 64*p];
    stage1<-1>(x, sA[f], t);
    __syncthreads();
    stage2<-1>(sA[f], sB[f], t);
    __syncthreads();
    stage3<-1>(sB[f], x, t);
#pragma unroll
    for (int q = 0; q < 8; q++) p0[q] = fmaf(x[q].x, x[q].x, x[q].y * x[q].y);
    // forward FFT of column 2f+1
#pragma unroll
    for (int p = 0; p < 8; p++) x[p] = ib1[t + 64*p];
    stage1<-1>(x, sA[f], t);
    __syncthreads();
    stage2<-1>(sA[f], sB[f], t);
    __syncthreads();
    stage3<-1>(sB[f], x, t);
    // z = P0 + i*P1 straight from registers, single packed inverse FFT
#pragma unroll
    for (int q = 0; q < 8; q++)
        x[q] = make_float2(p0[q], fmaf(x[q].x, x[q].x, x[q].y * x[q].y));
    stage1<1>(x, sA[f], t);
    __syncthreads();
    stage2<1>(sA[f], sB[f], t);
    __syncthreads();
    stage3<1>(sB[f], x, t);
#pragma unroll
    for (int q = 0; q < 8; q++) sA[f][SW(t + 64*q)] = x[q];
    __syncthreads();

    float2* ob = g_bufA + (size_t)img * AROWS * KXP;
#pragma unroll
    for (int it = 0; it < 2; it++) {
        int y = tid + it * 256;
        int u = y ^ 256;                 // rolled row index
        if (u <= 257) {
            int ym = (ELN - y) & (ELN - 1);
            float4* o = (float4*)(ob + (size_t)u * KXP + kx0);
#pragma unroll
            for (int f2 = 0; f2 < 4; f2++) {
                float2 Zy = sA[f2][SW(y)], Zm = sA[f2][SW(ym)];
                // G0 = (Z + conj(Zm))/2 ; G1 = (Z - conj(Zm))/(2i)
                o[f2] = make_float4(0.5f*(Zy.x + Zm.x), 0.5f*(Zy.y - Zm.y),
                                    0.5f*(Zy.y + Zm.y), 0.5f*(Zm.x - Zy.x));
            }
        }
    }
}

// ---- K3: inverse x-FFT of rows u=0..257 only (2 rows per FFT, Hermitian
//      packing). Full min/max from these rows (others are mirror duplicates).
//      Band rows [136,376] written to g_ac directly + via inversion mirror. ----
__global__ __launch_bounds__(256) void k_inv_x() {
    __shared__ float2 sA[4][ELN], sB[4][ELN];
    __shared__ float smn[8], smx[8];
    int tid = threadIdx.x, f = tid >> 6, t = tid & 63;
    int g = blockIdx.x, img = blockIdx.y;
    int p0 = min(g * 4, 125);            // pair index base (pairs 0..128)
    int u0 = p0 * 2;
    const float2* Ga = g_bufA + (size_t)img * AROWS * KXP + (size_t)(u0 + 2*f) * KXP;
    const float2* Gb = Ga + KXP;
    float2 x[8];
#pragma unroll
    for (int p = 0; p < 8; p++) {
        int kx = t + 64*p;
        if (kx <= 256) {
            float2 a = Ga[kx], b = Gb[kx];
            x[p] = make_float2(a.x - b.y, a.y + b.x);     // Ga + i*Gb
        } else {
            int m = ELN - kx;
            float2 a = Ga[m], b = Gb[m];
            x[p] = make_float2(a.x + b.y, b.x - a.y);     // conj(Ga) + i*conj(Gb)
        }
    }
    stage1<1>(x, sA[f], t);
    __syncthreads();
    stage2<1>(sA[f], sB[f], t);
    __syncthreads();
    stage3<1>(sB[f], x, t);
#pragma unroll
    for (int q = 0; q < 8; q++) sA[f][SW(t + 64*q)] = x[q];
    __syncthreads();

    float* ob = g_ac + (size_t)img * IMG_PIX;
    float lmin = 3.4e38f, lmax = -3.4e38f;
#pragma unroll
    for (int it = 0; it < 16; it++) {
        int idx = tid + it * 256;        // 0..4095 = 8 rows x 512
        int r8 = idx >> 9, xx = idx & 511;
        float2 v2 = sA[r8 >> 1][SW(xx)];
        float v = (r8 & 1) ? v2.y : v2.x;
        int u = u0 + r8;                 // 0..257
        int vcol = xx ^ 256;
        if (u >= BAND_LO) ob[(size_t)u * ELN + vcol] = v;       // u <= 257 < BAND_HI
        int um = (ELN - u) & (ELN - 1);  // mirror row
        if (um != u && um >= BAND_LO && um <= BAND_HI)
            ob[(size_t)um * ELN + ((ELN - vcol) & (ELN - 1))] = v;
        lmin = fminf(lmin, v);
        lmax = fmaxf(lmax, v);
    }
#pragma unroll
    for (int off = 16; off; off >>= 1) {
        lmin = fminf(lmin, __shfl_down_sync(0xFFFFFFFFu, lmin, off));
        lmax = fmaxf(lmax, __shfl_down_sync(0xFFFFFFFFu, lmax, off));
    }
    int wid = tid >> 5, lane = tid & 31;
    if (lane == 0) { smn[wid] = lmin; smx[wid] = lmax; }
    __syncthreads();
    if (tid == 0) {
        float mn = smn[0], mx = smx[0];
#pragma unroll
        for (int w = 1; w < 8; w++) { mn = fminf(mn, smn[w]); mx = fmaxf(mx, smx[w]); }
        atomicMin(&g_mm[2 * img],     fenc(mn));
        atomicMax(&g_mm[2 * img + 1], fenc(mx));
    }
}

// ---- K4: normalize + mask + MSE partial + concat outputs.
//      Outside the mask band the AC output is < 1.5e-8 -> write exact 0. ----
__global__ __launch_bounds__(256) void k_out(const float* __restrict__ in0,
                                             const float* __restrict__ in1,
                                             float* __restrict__ out) {
    __shared__ float red[8];
    int r = blockIdx.x, b = blockIdx.y, tid = threadIdx.x;
    const float* rin = in0 + (size_t)b * IMG_PIX + (size_t)r * ELN;
    const float* rtg = in1 + (size_t)b * IMG_PIX + (size_t)r * ELN;
    float* o1 = out + 1 + (size_t)b * (ELN * 1024) + (size_t)r * 1024;
    float* o2 = o1 + (size_t)BIMG * (ELN * 1024);

    if (r < BAND_LO || r > BAND_HI) {
#pragma unroll
        for (int c = tid; c < ELN; c += 256) {
            o1[c] = rin[c];  o1[ELN + c] = 0.0f;
            o2[c] = rtg[c];  o2[ELN + c] = 0.0f;
        }
        return;
    }

    float mnI = fdec(g_mm[2 * b]),          mxI = fdec(g_mm[2 * b + 1]);
    float mnT = fdec(g_mm[2 * (b + BIMG)]), mxT = fdec(g_mm[2 * (b + BIMG) + 1]);
    float sI = 1.0f / (mxI - mnI + 1e-12f);
    float sT = 1.0f / (mxT - mnT + 1e-12f);
    const float* ain = g_ac + (size_t)b * IMG_PIX + (size_t)r * ELN;
    const float* atg = g_ac + (size_t)(b + BIMG) * IMG_PIX + (size_t)r * ELN;
    float dy = (float)(r - 256);
    float acc = 0.0f;
#pragma unroll
    for (int c = tid; c < ELN; c += 256) {
        float dx = (float)(c - 256);
        float mask = __expf(-(dx * dx + dy * dy) * (1.0f / 800.0f));
        float ia = (ain[c] - mnI) * sI * mask;
        float ta = (atg[c] - mnT) * sT * mask;
        float d = ia - ta;
        acc += d * d;
        o1[c] = rin[c];  o1[ELN + c] = ia;
        o2[c] = rtg[c];  o2[ELN + c] = ta;
    }
#pragma unroll
    for (int off = 16; off; off >>= 1)
        acc += __shfl_down_sync(0xFFFFFFFFu, acc, off);
    int wid = tid >> 5, lane = tid & 31;
    if (lane == 0) red[wid] = acc;
    __syncthreads();
    if (tid == 0) {
        float s = 0.0f;
#pragma unroll
        for (int w = 0; w < 8; w++) s += red[w];
        atomicAdd(&g_diff, (double)s);
    }
}

__global__ void k_fin(float* __restrict__ out) {
    out[0] = (float)(g_diff / (double)((size_t)BIMG * IMG_PIX));
}

extern "C" void kernel_launch(void* const* d_in, const int* in_sizes, int n_in,
                              void* d_out, int out_size) {
    const float* in0 = (const float*)d_in[0];   // input  (64,1,512,512)
    const float* in1 = (const float*)d_in[1];   // target (64,1,512,512)
    float* out = (float*)d_out;                 // [diff | input_and_ac | target_and_ac]

    k_init<<<1, 128>>>();
    k_fwd_x<<<dim3(64, NIMG), 256>>>(in0, in1);
    k_mid<<<dim3(33, NIMG), 256>>>();
    k_inv_x<<<dim3(33, NIMG), 256>>>();
    k_out<<<dim3(ELN, BIMG), 256>>>(in0, in1, out);
    k_fin<<<1, 1>>>(out);
}

// round 17
// speedup vs baseline: 1.3477x; 1.1224x over previous
#include <cuda_runtime.h>

#define ELN 512
#define NIMG 128
#define BIMG 64
#define IMG_PIX (ELN*ELN)
#define OROW 1024            // output row stride (raw 512 | ac 512)
#define KXP 260              // padded half-spectrum width (257 used)
#define AROWS 258            // stored rows of rolled-AC spectrum (u = 0..257)
#define BAND_LO 136          // mask band: |u-256| <= 120
#define BAND_HI 376
#define BAND_N  (BAND_HI - BAND_LO + 1)
#define TWO_PI 6.28318530717958647692f

// Scratch (device globals; zero-initialized at load, padding never written)
__device__ float2 g_bufB[(size_t)NIMG * KXP * ELN];    // [img][kx 0..259][y]
__device__ float2 g_bufA[(size_t)NIMG * AROWS * KXP];  // [img][u 0..257][kx]
__device__ float  g_ac[(size_t)NIMG * IMG_PIX];
__device__ unsigned int g_mm[2 * NIMG];
__device__ double g_diff;

// XOR swizzle: conflict-free for (t+64p) reads and (8t+q)/(k+64j+8q) writes
#define SW(i) ((i) ^ ((i) >> 3))

// ---- monotone float <-> uint encoding for atomic min/max ----
__device__ __forceinline__ unsigned fenc(float f) {
    unsigned u = __float_as_uint(f);
    return (u & 0x80000000u) ? ~u : (u | 0x80000000u);
}
__device__ __forceinline__ float fdec(unsigned e) {
    return __uint_as_float((e & 0x80000000u) ? (e ^ 0x80000000u) : ~e);
}

__device__ __forceinline__ float2 cadd(float2 a, float2 b){ return make_float2(a.x+b.x, a.y+b.y); }
__device__ __forceinline__ float2 csub(float2 a, float2 b){ return make_float2(a.x-b.x, a.y-b.y); }
__device__ __forceinline__ float2 cmul(float2 a, float2 b){
    return make_float2(fmaf(a.x, b.x, -a.y*b.y), fmaf(a.x, b.y, a.y*b.x));
}
template<int SGN>
__device__ __forceinline__ float2 mul_si(float2 a){
    return (SGN > 0) ? make_float2(-a.y, a.x) : make_float2(a.y, -a.x);
}

// 8-point DFT in registers
template<int SGN>
__device__ __forceinline__ void dft8(float2* x){
    const float C = 0.70710678118654752440f;
    const float sg = (float)SGN;
    float2 F0 = cadd(x[0], x[4]), F1 = csub(x[0], x[4]);
    float2 G0 = cadd(x[2], x[6]), G1r = mul_si<SGN>(csub(x[2], x[6]));
    float2 H0 = cadd(x[1], x[5]), H1 = csub(x[1], x[5]);
    float2 I0 = cadd(x[3], x[7]), I1r = mul_si<SGN>(csub(x[3], x[7]));
    float2 E0 = cadd(F0, G0), E2 = csub(F0, G0);
    float2 E1 = cadd(F1, G1r), E3 = csub(F1, G1r);
    float2 O0 = cadd(H0, I0), O2 = csub(H0, I0);
    float2 O1 = cadd(H1, I1r), O3 = csub(H1, I1r);
    float2 W1O = make_float2(C*(O1.x - sg*O1.y), C*(O1.y + sg*O1.x));
    float2 W2O = make_float2(-sg*O2.y, sg*O2.x);
    float2 W3O = make_float2(C*(-O3.x - sg*O3.y), C*(sg*O3.x - O3.y));
    x[0] = cadd(E0, O0);  x[4] = csub(E0, O0);
    x[1] = cadd(E1, W1O); x[5] = csub(E1, W1O);
    x[2] = cadd(E2, W2O); x[6] = csub(E2, W2O);
    x[3] = cadd(E3, W3O); x[7] = csub(E3, W3O);
}

template<int SGN>
__device__ __forceinline__ void twiddle(float2* x, int j, float invL8){
    float ang = (float)SGN * TWO_PI * invL8 * (float)j;
    float s, c; __sincosf(ang, &s, &c);
    float2 w = make_float2(c, s), wq = w;
    x[1] = cmul(x[1], wq);
#pragma unroll
    for (int q = 2; q < 8; q++) { wq = cmul(wq, w); x[q] = cmul(x[q], wq); }
}

// Stage 1 (L=64,M=1): x in regs -> dft8 -> twiddle(j=t) -> smem dst[8t+q]
template<int SGN>
__device__ __forceinline__ void stage1(float2* x, float2* dst, int t){
    dft8<SGN>(x);
    twiddle<SGN>(x, t, 1.0f / 512.0f);
#pragma unroll
    for (int q = 0; q < 8; q++) dst[SW(8*t + q)] = x[q];
}
// Stage 2 (L=8,M=8): read src[t+64p] -> dft8 -> twiddle(j=t>>3) -> dst[k+64j+8q]
template<int SGN>
__device__ __forceinline__ void stage2(const float2* src, float2* dst, int t){
    float2 x[8];
#pragma unroll
    for (int p = 0; p < 8; p++) x[p] = src[SW(t + 64*p)];
    dft8<SGN>(x);
    twiddle<SGN>(x, t >> 3, 1.0f / 64.0f);
    int base = (t & 7) + 64 * (t >> 3);
#pragma unroll
    for (int q = 0; q < 8; q++) dst[SW(base + 8*q)] = x[q];
}
// Stage 3 (L=1,M=64): read src[t+64p] -> dft8. Result x[q] = element (t+64q).
template<int SGN>
__device__ __forceinline__ void stage3(const float2* src, float2* x, int t){
#pragma unroll
    for (int p = 0; p < 8; p++) x[p] = src[SW(t + 64*p)];
    dft8<SGN>(x);
}

// ---- init accumulators (graph-replay safe) ----
__global__ void k_init() {
    int i = threadIdx.x;
    if (i < NIMG) { g_mm[2*i] = 0xFFFFFFFFu; g_mm[2*i + 1] = 0u; }
    if (i == 0) g_diff = 0.0;
}

// ---- K1: mf0 + forward x-FFT of 2 packed real rows per FFT.
//      Raw rows are stored to the concat output FROM THE SAME REGISTERS
//      (no extra global reads); out-of-band AC slots zero-filled here.
//      Writes half-spectrum kx=0..256 transposed -> g_bufB [img][kx][y]. ----
__global__ __launch_bounds__(256) void k_fwd_x(const float* __restrict__ in0,
                                               const float* __restrict__ in1,
                                               float* __restrict__ out) {
    __shared__ float2 sA[4][ELN], sB[4][ELN];
    int tid = threadIdx.x, f = tid >> 6, t = tid & 63;
    int g = blockIdx.x, img = blockIdx.y;
    int y0 = g * 8;
    const float* src = (img < BIMG) ? in0 + (size_t)img * IMG_PIX
                                    : in1 + (size_t)(img - BIMG) * IMG_PIX;
    const float* ra = src + (size_t)(y0 + 2*f) * ELN;
    const float* rb = ra + ELN;
    // out: [diff | input_and_ac (64 img) | target_and_ac (64 img)], contiguous
    float* obase = out + 1 + (size_t)img * (ELN * OROW);
    float* oa = obase + (size_t)(y0 + 2*f) * OROW;
    float* ob2 = oa + OROW;
    float2 x[8];
#pragma unroll
    for (int p = 0; p < 8; p++) {
        float va = ra[t + 64*p], vb = rb[t + 64*p];
        oa[t + 64*p]  = va;                       // raw copy from registers
        ob2[t + 64*p] = vb;
        x[p] = make_float2(__expf(-8.0f * va * va), __expf(-8.0f * vb * vb));
    }
    // zero-fill AC slots of out-of-band rows (pure stores)
#pragma unroll
    for (int r8 = 0; r8 < 8; r8++) {
        int r = y0 + r8;
        if (r < BAND_LO || r > BAND_HI) {
            float* oz = obase + (size_t)r * OROW + ELN;
            for (int c = tid; c < ELN; c += 256) oz[c] = 0.0f;
        }
    }
    stage1<-1>(x, sA[f], t);
    __syncthreads();
    stage2<-1>(sA[f], sB[f], t);
    __syncthreads();
    stage3<-1>(sB[f], x, t);
#pragma unroll
    for (int q = 0; q < 8; q++) sA[f][SW(t + 64*q)] = x[q];
    __syncthreads();

    float2* obuf = g_bufB + (size_t)img * KXP * ELN;
    for (int kx = tid; kx <= 256; kx += 256) {
        int m = (ELN - kx) & (ELN - 1);
        float4* o = (float4*)(obuf + (size_t)kx * ELN + y0);
#pragma unroll
        for (int f2 = 0; f2 < 4; f2++) {
            float2 z  = sA[f2][SW(kx)];
            float2 zm = sA[f2][SW(m)];
            // F_A = (Z + conj(Zm))/2 ; F_B = (Z - conj(Zm))/(2i)
            o[f2] = make_float4(0.5f*(z.x + zm.x), 0.5f*(z.y - zm.y),
                                0.5f*(z.y + zm.y), 0.5f*(zm.x - z.x));
        }
    }
}

// ---- K2 (R9 form): fwd y-FFT + |.|^2 + inv y-FFT for kx cols 0..256.
//      Power feeds inverse with NO exchange. Transposed write with y-roll,
//      rows u <= 257 kept -> g_bufA [img][u][kx]. 4 cols/block. ----
__global__ __launch_bounds__(256) void k_mid() {
    __shared__ float2 sA[4][ELN], sB[4][ELN];
    int tid = threadIdx.x, f = tid >> 6, t = tid & 63;
    int g = blockIdx.x, img = blockIdx.y;
    int kx0 = g * 4;
    const float2* ib = g_bufB + (size_t)img * KXP * ELN + (size_t)(kx0 + f) * ELN;
    float2 x[8];
#pragma unroll
    for (int p = 0; p < 8; p++) x[p] = ib[t + 64*p];
    stage1<-1>(x, sA[f], t);
    __syncthreads();
    stage2<-1>(sA[f], sB[f], t);
    __syncthreads();
    stage3<-1>(sB[f], x, t);
    // |.|^2 in regs, straight into inverse stage 1 (pattern matches)
#pragma unroll
    for (int p = 0; p < 8; p++)
        x[p] = make_float2(fmaf(x[p].x, x[p].x, x[p].y * x[p].y), 0.0f);
    stage1<1>(x, sA[f], t);
    __syncthreads();
    stage2<1>(sA[f], sB[f], t);
    __syncthreads();
    stage3<1>(sB[f], x, t);
#pragma unroll
    for (int q = 0; q < 8; q++) sA[f][SW(t + 64*q)] = x[q];
    __syncthreads();

    float2* ob = g_bufA + (size_t)img * AROWS * KXP;
#pragma unroll
    for (int it = 0; it < 2; it++) {
        int y = tid + it * 256;
        int u = y ^ 256;                 // rolled row index
        if (u <= 257) {
            float2 v0 = sA[0][SW(y)], v1 = sA[1][SW(y)];
            float2 v2 = sA[2][SW(y)], v3 = sA[3][SW(y)];
            float4* o = (float4*)(ob + (size_t)u * KXP + kx0);
            o[0] = make_float4(v0.x, v0.y, v1.x, v1.y);
            o[1] = make_float4(v2.x, v2.y, v3.x, v3.y);
        }
    }
}

// ---- K3: inverse x-FFT of rows u=0..257 only (2 rows per FFT, Hermitian
//      packing). Full min/max from these rows (others are mirror duplicates).
//      Band rows [136,376] written to g_ac directly + via inversion mirror. ----
__global__ __launch_bounds__(256) void k_inv_x() {
    __shared__ float2 sA[4][ELN], sB[4][ELN];
    __shared__ float smn[8], smx[8];
    int tid = threadIdx.x, f = tid >> 6, t = tid & 63;
    int g = blockIdx.x, img = blockIdx.y;
    int p0 = min(g * 4, 125);            // pair index base (pairs 0..128)
    int u0 = p0 * 2;
    const float2* Ga = g_bufA + (size_t)img * AROWS * KXP + (size_t)(u0 + 2*f) * KXP;
    const float2* Gb = Ga + KXP;
    float2 x[8];
#pragma unroll
    for (int p = 0; p < 8; p++) {
        int kx = t + 64*p;
        if (kx <= 256) {
            float2 a = Ga[kx], b = Gb[kx];
            x[p] = make_float2(a.x - b.y, a.y + b.x);     // Ga + i*Gb
        } else {
            int m = ELN - kx;
            float2 a = Ga[m], b = Gb[m];
            x[p] = make_float2(a.x + b.y, b.x - a.y);     // conj(Ga) + i*conj(Gb)
        }
    }
    stage1<1>(x, sA[f], t);
    __syncthreads();
    stage2<1>(sA[f], sB[f], t);
    __syncthreads();
    stage3<1>(sB[f], x, t);
#pragma unroll
    for (int q = 0; q < 8; q++) sA[f][SW(t + 64*q)] = x[q];
    __syncthreads();

    float* ob = g_ac + (size_t)img * IMG_PIX;
    float lmin = 3.4e38f, lmax = -3.4e38f;
#pragma unroll
    for (int it = 0; it < 16; it++) {
        int idx = tid + it * 256;        // 0..4095 = 8 rows x 512
        int r8 = idx >> 9, xx = idx & 511;
        float2 v2 = sA[r8 >> 1][SW(xx)];
        float v = (r8 & 1) ? v2.y : v2.x;
        int u = u0 + r8;                 // 0..257
        int vcol = xx ^ 256;
        if (u >= BAND_LO) ob[(size_t)u * ELN + vcol] = v;       // u <= 257 < BAND_HI
        int um = (ELN - u) & (ELN - 1);  // mirror row
        if (um != u && um >= BAND_LO && um <= BAND_HI)
            ob[(size_t)um * ELN + ((ELN - vcol) & (ELN - 1))] = v;
        lmin = fminf(lmin, v);
        lmax = fmaxf(lmax, v);
    }
#pragma unroll
    for (int off = 16; off; off >>= 1) {
        lmin = fminf(lmin, __shfl_down_sync(0xFFFFFFFFu, lmin, off));
        lmax = fmaxf(lmax, __shfl_down_sync(0xFFFFFFFFu, lmax, off));
    }
    int wid = tid >> 5, lane = tid & 31;
    if (lane == 0) { smn[wid] = lmin; smx[wid] = lmax; }
    __syncthreads();
    if (tid == 0) {
        float mn = smn[0], mx = smx[0];
#pragma unroll
        for (int w = 1; w < 8; w++) { mn = fminf(mn, smn[w]); mx = fmaxf(mx, smx[w]); }
        atomicMin(&g_mm[2 * img],     fenc(mn));
        atomicMax(&g_mm[2 * img + 1], fenc(mx));
    }
}

// ---- K4: band rows only: normalize + mask + MSE partial + AC writes ----
__global__ __launch_bounds__(256) void k_out(float* __restrict__ out) {
    __shared__ float red[8];
    int r = BAND_LO + blockIdx.x, b = blockIdx.y, tid = threadIdx.x;
    float mnI = fdec(g_mm[2 * b]),          mxI = fdec(g_mm[2 * b + 1]);
    float mnT = fdec(g_mm[2 * (b + BIMG)]), mxT = fdec(g_mm[2 * (b + BIMG) + 1]);
    float sI = 1.0f / (mxI - mnI + 1e-12f);
    float sT = 1.0f / (mxT - mnT + 1e-12f);
    const float* ain = g_ac + (size_t)b * IMG_PIX + (size_t)r * ELN;
    const float* atg = g_ac + (size_t)(b + BIMG) * IMG_PIX + (size_t)r * ELN;
    float* o1 = out + 1 + (size_t)b * (ELN * OROW) + (size_t)r * OROW + ELN;
    float* o2 = o1 + (size_t)BIMG * (ELN * OROW);
    float dy = (float)(r - 256);
    float acc = 0.0f;
#pragma unroll
    for (int c = tid; c < ELN; c += 256) {
        float dx = (float)(c - 256);
        float mask = __expf(-(dx * dx + dy * dy) * (1.0f / 800.0f));
        float ia = (ain[c] - mnI) * sI * mask;
        float ta = (atg[c] - mnT) * sT * mask;
        float d = ia - ta;
        acc += d * d;
        o1[c] = ia;
        o2[c] = ta;
    }
#pragma unroll
    for (int off = 16; off; off >>= 1)
        acc += __shfl_down_sync(0xFFFFFFFFu, acc, off);
    int wid = tid >> 5, lane = tid & 31;
    if (lane == 0) red[wid] = acc;
    __syncthreads();
    if (tid == 0) {
        float s = 0.0f;
#pragma unroll
        for (int w = 0; w < 8; w++) s += red[w];
        atomicAdd(&g_diff, (double)s);
    }
}

__global__ void k_fin(float* __restrict__ out) {
    out[0] = (float)(g_diff / (double)((size_t)BIMG * IMG_PIX));
}

extern "C" void kernel_launch(void* const* d_in, const int* in_sizes, int n_in,
                              void* d_out, int out_size) {
    const float* in0 = (const float*)d_in[0];   // input  (64,1,512,512)
    const float* in1 = (const float*)d_in[1];   // target (64,1,512,512)
    float* out = (float*)d_out;                 // [diff | input_and_ac | target_and_ac]

    k_init<<<1, 128>>>();
    k_fwd_x<<<dim3(64, NIMG), 256>>>(in0, in1, out);
    k_mid<<<dim3(65, NIMG), 256>>>();
    k_inv_x<<<dim3(33, NIMG), 256>>>();
    k_out<<<dim3(BAND_N, BIMG), 256>>>(out);
    k_fin<<<1, 1>>>(out);
}